// round 5
// baseline (speedup 1.0000x reference)
#include <cuda_runtime.h>
#include <math.h>

// Problem dims
#define B_   32
#define L_   4096
#define DIN  16
#define H_   128
#define N2_  32
#define NL_  4
#define DOUT 8

// ---------------- scratch (device globals; no allocations allowed) ----------
__device__ float g_u[B_ * H_ * L_];       // running activation, (b,h,l)
__device__ float g_y[B_ * H_ * L_];       // conv+gelu output, (b,h,l)
__device__ float g_wre[NL_ * H_ * N2_];
__device__ float g_wim[NL_ * H_ * N2_];
__device__ float g_c1[NL_ * H_ * N2_];
__device__ float g_c2[NL_ * H_ * N2_];
__device__ float g_pool[B_ * H_];

// ---------------- f32x2 packed FMA helpers (Blackwell FFMA2) ----------------
__device__ __forceinline__ unsigned long long pack2(float a, float b) {
    unsigned long long r;
    asm("mov.b64 %0, {%1,%2};" : "=l"(r) : "f"(a), "f"(b));
    return r;
}
__device__ __forceinline__ void unpack2(unsigned long long v, float& a, float& b) {
    asm("mov.b64 {%0,%1}, %2;" : "=f"(a), "=f"(b) : "l"(v));
}
__device__ __forceinline__ unsigned long long fma2(unsigned long long a,
                                                   unsigned long long b,
                                                   unsigned long long c) {
    unsigned long long d;
    asm("fma.rn.f32x2 %0, %1, %2, %3;" : "=l"(d) : "l"(a), "l"(b), "l"(c));
    return d;
}

__device__ __forceinline__ float sigmoidf_(float x) {
    return 1.0f / (1.0f + expf(-x));
}

// ---------------- kernel 0: precompute SSM coefficients ---------------------
__global__ void precompute_kernel(const float* __restrict__ log_dt,
                                  const float* __restrict__ log_A_real,
                                  const float* __restrict__ A_imag,
                                  const float* __restrict__ C_re,
                                  const float* __restrict__ C_im) {
    int idx = blockIdx.x * blockDim.x + threadIdx.x;   // NL*H*N2 = 16384
    if (idx >= NL_ * H_ * N2_) return;
    int l = idx / (H_ * N2_);
    int h = (idx / N2_) % H_;

    float dt  = expf(log_dt[l * H_ + h]);
    float are = -expf(log_A_real[idx]);
    float aim = A_imag[idx];
    float dre = dt * are;
    float dim = dt * aim;
    float m   = expf(dre);
    float wre = m * cosf(dim);
    float wim = m * sinf(dim);
    // (w - 1) / A
    float nre = wre - 1.0f, nim = wim;
    float den = are * are + aim * aim;
    float inv = 1.0f / den;
    float qre = (nre * are + nim * aim) * inv;
    float qim = (nim * are - nre * aim) * inv;
    float cre = C_re[idx], cim = C_im[idx];
    float tre = cre * qre - cim * qim;
    float tim = cre * qim + cim * qre;
    g_wre[idx] = wre;
    g_wim[idx] = wim;
    g_c1[idx]  = 2.0f * tre;
    g_c2[idx]  = -2.0f * tim;
}

// ---------------- kernel 1: encoder  u[b,h,l] = x[b,l,:]·enc_w[h,:] + b -----
__global__ void encoder_kernel(const float* __restrict__ x,
                               const float* __restrict__ enc_w,
                               const float* __restrict__ enc_b) {
    __shared__ float sx[64 * 17];   // [p][d], padded
    __shared__ float sw[H_ * DIN];
    __shared__ float sb[H_];
    int t = threadIdx.x;            // 256
    int b = blockIdx.y;
    int l0 = blockIdx.x * 64;

    const float* xb = x + ((size_t)b * L_ + l0) * DIN;
    for (int i = t; i < 64 * DIN; i += 256) {
        int p = i >> 4, d = i & 15;
        sx[p * 17 + d] = xb[i];
    }
    for (int i = t; i < H_ * DIN; i += 256) sw[i] = enc_w[i];
    if (t < H_) sb[t] = enc_b[t];
    __syncthreads();

    int ubase = b * H_ * L_;
    for (int i = t; i < H_ * 64; i += 256) {
        int h = i >> 6, p = i & 63;
        float acc = sb[h];
#pragma unroll
        for (int d = 0; d < DIN; d++)
            acc = fmaf(sw[(h << 4) + d], sx[p * 17 + d], acc);
        g_u[ubase + (h << 12) + l0 + p] = acc;
    }
}

// ---------------- kernel 2: SSM scan + D skip + GELU ------------------------
// 2 sequences per warp; 16 lanes per sequence; 2 complex states per lane.
__global__ void scan_kernel(int layer, const float* __restrict__ Dl) {
    const unsigned F = 0xffffffffu;
    int t = threadIdx.x;
    int warpG = blockIdx.x * 8 + (t >> 5);
    int lane  = t & 31;
    int half  = lane >> 4;
    int lane16 = lane & 15;
    int seq = warpG * 2 + half;            // 0 .. B*H-1
    int h = seq & (H_ - 1);

    const float* z = g_u + (size_t)seq * L_;
    float* yo = g_y + (size_t)seq * L_;

    int cbase = layer * (H_ * N2_) + h * N2_ + lane16 * 2;
    float wre0 = g_wre[cbase],     wim0 = g_wim[cbase];
    float wre1 = g_wre[cbase + 1], wim1 = g_wim[cbase + 1];
    float c10 = g_c1[cbase],     c20 = g_c2[cbase];
    float c11 = g_c1[cbase + 1], c21 = g_c2[cbase + 1];
    float Dh = Dl[h];

    float s0re = 0.f, s0im = 0.f, s1re = 0.f, s1im = 0.f;
    int srcb = lane & 16;

    for (int t0 = 0; t0 < L_; t0 += 16) {
        float zb = z[t0 + lane16];
        float keep = 0.f;
#pragma unroll
        for (int j = 0; j < 16; j++) {
            float zj = __shfl_sync(F, zb, srcb + j);
            float a0 = fmaf(wre0, s0re, fmaf(-wim0, s0im, zj));
            float b0 = fmaf(wre0, s0im, wim0 * s0re);
            s0re = a0; s0im = b0;
            float a1 = fmaf(wre1, s1re, fmaf(-wim1, s1im, zj));
            float b1 = fmaf(wre1, s1im, wim1 * s1re);
            s1re = a1; s1im = b1;
            float c = fmaf(c10, s0re, fmaf(c20, s0im,
                      fmaf(c11, s1re, c21 * s1im)));
            c += __shfl_xor_sync(F, c, 1);
            c += __shfl_xor_sync(F, c, 2);
            c += __shfl_xor_sync(F, c, 4);
            c += __shfl_xor_sync(F, c, 8);
            float yraw = fmaf(Dh, zj, c);
            keep = (lane16 == j) ? yraw : keep;
        }
        // exact GELU
        float g = 0.5f * keep * (1.0f + erff(keep * 0.7071067811865475f));
        yo[t0 + lane16] = g;
    }
}

// ---------------- kernel 3: 1x1 conv -> GLU -> residual -> LayerNorm --------
// One block handles (b, 128 positions). Dynamic smem: Wa/Wg half (64KB) +
// y tile (64KB) + result tile (64KB) + small vectors.
#define GLU_SMEM_FLOATS (16384 * 3 + 256 + 128 * 4)
__global__ void glu_ln_kernel(const float* __restrict__ conv_w_l,
                              const float* __restrict__ conv_b_l,
                              const float* __restrict__ ln_w_l,
                              const float* __restrict__ ln_b_l) {
    extern __shared__ float sm[];
    float* sW   = sm;                 // 16384 : current weight half [o*128+h]
    float* sY   = sm + 16384;         // 16384 : y tile [h*128+p]
    float* sR   = sm + 32768;         // 16384 : a-acc, then result [o*128+p]
    float* sBias = sm + 49152;        // 256
    float* sLnw = sm + 49408;         // 128
    float* sLnb = sm + 49536;         // 128
    float* sMu  = sm + 49664;         // 128
    float* sRs  = sm + 49792;         // 128

    int t = threadIdx.x;              // 256
    int b = blockIdx.x >> 5;
    int l0 = (blockIdx.x & 31) << 7;  // 128 positions
    int ubase = b * H_ * L_;

    // stage Wa + y tile + vectors
    for (int i = t; i < 16384; i += 256) sW[i] = conv_w_l[i];
    for (int i = t; i < 16384; i += 256) {
        int h = i >> 7, p = i & 127;
        sY[i] = g_y[ubase + (h << 12) + l0 + p];
    }
    if (t < 256) sBias[t] = conv_b_l[t];
    if (t < 128) { sLnw[t] = ln_w_l[t]; sLnb[t] = ln_b_l[t]; }
    __syncthreads();

    int w = t >> 5, lane = t & 31;
    int p0 = lane << 2;
    int obase = w * 16;

    // ---- pass A: a = Wa @ y + ba ----
    for (int ob = 0; ob < 4; ob++) {
        int o = obase + ob * 4;
        unsigned long long acc[4][2];
#pragma unroll
        for (int k = 0; k < 4; k++) { acc[k][0] = 0ull; acc[k][1] = 0ull; }
#pragma unroll 2
        for (int h = 0; h < H_; h++) {
            float4 y4 = *(const float4*)&sY[(h << 7) + p0];
            unsigned long long ylo = pack2(y4.x, y4.y);
            unsigned long long yhi = pack2(y4.z, y4.w);
#pragma unroll
            for (int k = 0; k < 4; k++) {
                float wv = sW[((o + k) << 7) + h];
                unsigned long long wp = pack2(wv, wv);
                acc[k][0] = fma2(wp, ylo, acc[k][0]);
                acc[k][1] = fma2(wp, yhi, acc[k][1]);
            }
        }
#pragma unroll
        for (int k = 0; k < 4; k++) {
            float a0, a1, a2, a3;
            unpack2(acc[k][0], a0, a1);
            unpack2(acc[k][1], a2, a3);
            float bias = sBias[o + k];
            float4 v = make_float4(a0 + bias, a1 + bias, a2 + bias, a3 + bias);
            *(float4*)&sR[((o + k) << 7) + p0] = v;
        }
    }
    __syncthreads();

    // reload Wg half
    for (int i = t; i < 16384; i += 256) sW[i] = conv_w_l[16384 + i];
    __syncthreads();

    // ---- pass B: g, then GLU + residual ----
    for (int ob = 0; ob < 4; ob++) {
        int o = obase + ob * 4;
        unsigned long long acc[4][2];
#pragma unroll
        for (int k = 0; k < 4; k++) { acc[k][0] = 0ull; acc[k][1] = 0ull; }
#pragma unroll 2
        for (int h = 0; h < H_; h++) {
            float4 y4 = *(const float4*)&sY[(h << 7) + p0];
            unsigned long long ylo = pack2(y4.x, y4.y);
            unsigned long long yhi = pack2(y4.z, y4.w);
#pragma unroll
            for (int k = 0; k < 4; k++) {
                float wv = sW[((o + k) << 7) + h];
                unsigned long long wp = pack2(wv, wv);
                acc[k][0] = fma2(wp, ylo, acc[k][0]);
                acc[k][1] = fma2(wp, yhi, acc[k][1]);
            }
        }
#pragma unroll
        for (int k = 0; k < 4; k++) {
            float g0, g1, g2, g3;
            unpack2(acc[k][0], g0, g1);
            unpack2(acc[k][1], g2, g3);
            float bias = sBias[128 + o + k];
            float4 av = *(const float4*)&sR[((o + k) << 7) + p0];
            float4 uv = *(const float4*)&g_u[ubase + ((o + k) << 12) + l0 + p0];
            float4 r;
            r.x = fmaf(av.x, sigmoidf_(g0 + bias), uv.x);
            r.y = fmaf(av.y, sigmoidf_(g1 + bias), uv.y);
            r.z = fmaf(av.z, sigmoidf_(g2 + bias), uv.z);
            r.w = fmaf(av.w, sigmoidf_(g3 + bias), uv.w);
            *(float4*)&sR[((o + k) << 7) + p0] = r;
        }
    }
    __syncthreads();

    // ---- layernorm over H per position ----
    if (t < 128) {
        int p = t;
        float s = 0.f, ss = 0.f;
        for (int h = 0; h < H_; h++) {
            float v = sR[(h << 7) + p];
            s += v;
            ss = fmaf(v, v, ss);
        }
        float mu = s * (1.0f / H_);
        float var = ss * (1.0f / H_) - mu * mu;
        sMu[p] = mu;
        sRs[p] = rsqrtf(var + 1e-5f);
    }
    __syncthreads();

    for (int i = t; i < 16384; i += 256) {
        int h = i >> 7, p = i & 127;
        float val = (sR[i] - sMu[p]) * sRs[p] * sLnw[h] + sLnb[h];
        g_u[ubase + (h << 12) + l0 + p] = val;
    }
}

// ---------------- kernel 4: mean-pool over L --------------------------------
__global__ void pool_kernel() {
    __shared__ float red[256];
    int t = threadIdx.x;
    const float* p = g_u + (size_t)blockIdx.x * L_;
    float s = 0.f;
    for (int i = t; i < L_; i += 256) s += p[i];
    red[t] = s;
    __syncthreads();
    for (int k = 128; k > 0; k >>= 1) {
        if (t < k) red[t] += red[t + k];
        __syncthreads();
    }
    if (t == 0) g_pool[blockIdx.x] = red[0] * (1.0f / L_);
}

// ---------------- kernel 5: decoder -----------------------------------------
__global__ void decode_kernel(const float* __restrict__ dec_w,
                              const float* __restrict__ dec_b,
                              float* __restrict__ pred) {
    int t = threadIdx.x;
    if (t >= B_ * DOUT) return;
    int b = t >> 3, o = t & 7;
    float acc = dec_b[o];
    for (int h = 0; h < H_; h++)
        acc = fmaf(dec_w[o * H_ + h], g_pool[b * H_ + h], acc);
    pred[t] = 1.0f / (1.0f + expf(-acc));
}

// ---------------- kernel 6: transpose (b,h,l) -> emb (b,l,h) -----------------
__global__ void transpose_kernel(float* __restrict__ emb) {
    __shared__ float tile[32][33];
    int b = blockIdx.z;
    int h0 = blockIdx.y * 32;
    int l0 = blockIdx.x * 32;
    int tx = threadIdx.x, ty = threadIdx.y;
#pragma unroll
    for (int i = 0; i < 32; i += 8)
        tile[ty + i][tx] = g_u[((b * H_ + h0 + ty + i) << 12) + l0 + tx];
    __syncthreads();
#pragma unroll
    for (int i = 0; i < 32; i += 8)
        emb[((size_t)(b * L_ + l0 + ty + i)) * H_ + h0 + tx] = tile[tx][ty + i];
}

// ---------------- launch ------------------------------------------------------
extern "C" void kernel_launch(void* const* d_in, const int* in_sizes, int n_in,
                              void* d_out, int out_size) {
    const float* x          = (const float*)d_in[0];
    // d_in[1] = times (unused)
    const float* enc_w      = (const float*)d_in[2];
    const float* enc_b      = (const float*)d_in[3];
    const float* log_dt     = (const float*)d_in[4];
    const float* log_A_real = (const float*)d_in[5];
    const float* A_imag     = (const float*)d_in[6];
    const float* C_re       = (const float*)d_in[7];
    const float* C_im       = (const float*)d_in[8];
    const float* Dskip      = (const float*)d_in[9];
    const float* conv_w     = (const float*)d_in[10];
    const float* conv_b     = (const float*)d_in[11];
    const float* ln_w       = (const float*)d_in[12];
    const float* ln_b       = (const float*)d_in[13];
    const float* dec_w      = (const float*)d_in[14];
    const float* dec_b      = (const float*)d_in[15];

    float* out = (float*)d_out;
    float* pred = out;           // (B, DOUT) = 256 floats
    float* emb  = out + B_ * DOUT;

    static const size_t glu_smem = GLU_SMEM_FLOATS * sizeof(float);
    cudaFuncSetAttribute(glu_ln_kernel,
                         cudaFuncAttributeMaxDynamicSharedMemorySize,
                         (int)glu_smem);

    precompute_kernel<<<(NL_ * H_ * N2_ + 255) / 256, 256>>>(
        log_dt, log_A_real, A_imag, C_re, C_im);

    encoder_kernel<<<dim3(L_ / 64, B_), 256>>>(x, enc_w, enc_b);

    for (int l = 0; l < NL_; l++) {
        scan_kernel<<<(B_ * H_ / 2) / 8, 256>>>(l, Dskip + l * H_);
        glu_ln_kernel<<<B_ * (L_ / 128), 256, glu_smem>>>(
            conv_w + (size_t)l * 2 * H_ * H_,
            conv_b + (size_t)l * 2 * H_,
            ln_w + (size_t)l * H_,
            ln_b + (size_t)l * H_);
    }

    pool_kernel<<<B_ * H_, 256>>>();
    decode_kernel<<<1, 256>>>(dec_w, dec_b, pred);
    transpose_kernel<<<dim3(L_ / 32, H_ / 32, B_), dim3(32, 8)>>>(emb);
}

// round 6
// speedup vs baseline: 1.3466x; 1.3466x over previous
#include <cuda_runtime.h>
#include <math.h>

// Problem dims
#define B_   32
#define L_   4096
#define DIN  16
#define H_   128
#define N2_  32
#define NL_  4
#define DOUT 8

// ---------------- scratch (device globals; no allocations allowed) ----------
__device__ float g_u[B_ * H_ * L_];       // running activation, (b,h,l)
__device__ float g_y[B_ * H_ * L_];       // conv+gelu output, (b,h,l)
__device__ float g_wre[NL_ * H_ * N2_];
__device__ float g_wim[NL_ * H_ * N2_];
__device__ float g_c1[NL_ * H_ * N2_];
__device__ float g_c2[NL_ * H_ * N2_];
__device__ float g_pool[B_ * H_];

typedef unsigned long long u64;

// ---------------- f32x2 packed FMA helpers (Blackwell FFMA2) ----------------
__device__ __forceinline__ u64 pack2(float a, float b) {
    u64 r;
    asm("mov.b64 %0, {%1,%2};" : "=l"(r) : "f"(a), "f"(b));
    return r;
}
__device__ __forceinline__ void unpack2(u64 v, float& a, float& b) {
    asm("mov.b64 {%0,%1}, %2;" : "=f"(a), "=f"(b) : "l"(v));
}
__device__ __forceinline__ u64 fma2(u64 a, u64 b, u64 c) {
    u64 d;
    asm("fma.rn.f32x2 %0, %1, %2, %3;" : "=l"(d) : "l"(a), "l"(b), "l"(c));
    return d;
}

__device__ __forceinline__ float sigmoidf_(float x) {
    return 1.0f / (1.0f + expf(-x));
}

// ---------------- kernel 0: precompute SSM coefficients ---------------------
__global__ void precompute_kernel(const float* __restrict__ log_dt,
                                  const float* __restrict__ log_A_real,
                                  const float* __restrict__ A_imag,
                                  const float* __restrict__ C_re,
                                  const float* __restrict__ C_im) {
    int idx = blockIdx.x * blockDim.x + threadIdx.x;   // NL*H*N2 = 16384
    if (idx >= NL_ * H_ * N2_) return;
    int l = idx / (H_ * N2_);
    int h = (idx / N2_) % H_;

    float dt  = expf(log_dt[l * H_ + h]);
    float are = -expf(log_A_real[idx]);
    float aim = A_imag[idx];
    float dre = dt * are;
    float dim = dt * aim;
    float m   = expf(dre);
    float wre = m * cosf(dim);
    float wim = m * sinf(dim);
    // (w - 1) / A
    float nre = wre - 1.0f, nim = wim;
    float den = are * are + aim * aim;
    float inv = 1.0f / den;
    float qre = (nre * are + nim * aim) * inv;
    float qim = (nim * are - nre * aim) * inv;
    float cre = C_re[idx], cim = C_im[idx];
    float tre = cre * qre - cim * qim;
    float tim = cre * qim + cim * qre;
    g_wre[idx] = wre;
    g_wim[idx] = wim;
    g_c1[idx]  = 2.0f * tre;
    g_c2[idx]  = -2.0f * tim;
}

// ---------------- kernel 1: encoder  u[b,h,l] = x[b,l,:]·enc_w[h,:] + b -----
__global__ void encoder_kernel(const float* __restrict__ x,
                               const float* __restrict__ enc_w,
                               const float* __restrict__ enc_b) {
    __shared__ float sx[64 * 17];   // [p][d], padded
    __shared__ float sw[H_ * DIN];
    __shared__ float sb[H_];
    int t = threadIdx.x;            // 256
    int b = blockIdx.y;
    int l0 = blockIdx.x * 64;

    const float* xb = x + ((size_t)b * L_ + l0) * DIN;
    for (int i = t; i < 64 * DIN; i += 256) {
        int p = i >> 4, d = i & 15;
        sx[p * 17 + d] = xb[i];
    }
    for (int i = t; i < H_ * DIN; i += 256) sw[i] = enc_w[i];
    if (t < H_) sb[t] = enc_b[t];
    __syncthreads();

    int ubase = b * H_ * L_;
    for (int i = t; i < H_ * 64; i += 256) {
        int h = i >> 6, p = i & 63;
        float acc = sb[h];
#pragma unroll
        for (int d = 0; d < DIN; d++)
            acc = fmaf(sw[(h << 4) + d], sx[p * 17 + d], acc);
        g_u[ubase + (h << 12) + l0 + p] = acc;
    }
}

// ---------------- kernel 2: SSM scan + D skip + GELU (f32x2) ----------------
// 8 lanes per sequence, 4 complex states per lane packed as 2 f32x2 pairs.
// 4 sequences per warp. 12 fma2 + 4 shfl per warp-step (4 seq-steps).
__global__ void scan_kernel(int layer, const float* __restrict__ Dl) {
    const unsigned F = 0xffffffffu;
    const u64 Z0 = 0ull;
    int t = threadIdx.x;                    // 128
    int warpId = blockIdx.x * 4 + (t >> 5); // 0..1023
    int lane = t & 31;
    int lane8 = lane & 7;
    int g = lane >> 3;
    int seq = warpId * 4 + g;               // 0 .. B*H-1
    int h = seq & (H_ - 1);

    const float* z = g_u + (size_t)seq * L_;
    float* yo = g_y + (size_t)seq * L_;

    int cb = layer * (H_ * N2_) + h * N2_ + lane8 * 4;
    u64 wreA = pack2(g_wre[cb + 0], g_wre[cb + 1]);
    u64 wreB = pack2(g_wre[cb + 2], g_wre[cb + 3]);
    u64 wimA = pack2(g_wim[cb + 0], g_wim[cb + 1]);
    u64 wimB = pack2(g_wim[cb + 2], g_wim[cb + 3]);
    u64 nwimA = pack2(-g_wim[cb + 0], -g_wim[cb + 1]);
    u64 nwimB = pack2(-g_wim[cb + 2], -g_wim[cb + 3]);
    u64 c1A = pack2(g_c1[cb + 0], g_c1[cb + 1]);
    u64 c1B = pack2(g_c1[cb + 2], g_c1[cb + 3]);
    u64 c2A = pack2(g_c2[cb + 0], g_c2[cb + 1]);
    u64 c2B = pack2(g_c2[cb + 2], g_c2[cb + 3]);
    float Dh = Dl[h];

    u64 sreA = Z0, simA = Z0, sreB = Z0, simB = Z0;
    int srcb = lane & 24;

    for (int t0 = 0; t0 < L_; t0 += 8) {
        float zb = z[t0 + lane8];
        float keep = 0.f;
#pragma unroll
        for (int j = 0; j < 8; j++) {
            float zj = __shfl_sync(F, zb, srcb + j);
            u64 z2 = pack2(zj, zj);
            u64 nreA = fma2(wreA, sreA, fma2(nwimA, simA, z2));
            u64 nimA = fma2(wreA, simA, fma2(wimA, sreA, Z0));
            u64 nreB = fma2(wreB, sreB, fma2(nwimB, simB, z2));
            u64 nimB = fma2(wreB, simB, fma2(wimB, sreB, Z0));
            sreA = nreA; simA = nimA; sreB = nreB; simB = nimB;
            u64 acc = fma2(c1A, sreA,
                      fma2(c2A, simA,
                      fma2(c1B, sreB,
                      fma2(c2B, simB, Z0))));
            float a0, a1;
            unpack2(acc, a0, a1);
            float c = a0 + a1;
            c += __shfl_xor_sync(F, c, 1);
            c += __shfl_xor_sync(F, c, 2);
            c += __shfl_xor_sync(F, c, 4);
            float yraw = fmaf(Dh, zj, c);
            keep = (lane8 == j) ? yraw : keep;
        }
        // exact GELU
        float gv = 0.5f * keep * (1.0f + erff(keep * 0.7071067811865475f));
        yo[t0 + lane8] = gv;
    }
}

// ---------------- kernel 3: 1x1 conv -> GLU -> residual -> LayerNorm --------
// 512 threads; warp owns 8 output channels x 128 positions (4 per lane).
// Results live in registers; LN via 16KB partial-sum smem reduction.
__device__ __forceinline__ void mm8x4(const float* __restrict__ sW,
                                      const float* __restrict__ sY,
                                      int o0, int p0, float out[8][4]) {
    u64 acc[8][2];
#pragma unroll
    for (int k = 0; k < 8; k++) { acc[k][0] = 0ull; acc[k][1] = 0ull; }
#pragma unroll 2
    for (int h = 0; h < H_; h += 4) {
        u64 ylo[4], yhi[4];
#pragma unroll
        for (int i = 0; i < 4; i++) {
            float4 y4 = *(const float4*)&sY[((h + i) << 7) + p0];
            ylo[i] = pack2(y4.x, y4.y);
            yhi[i] = pack2(y4.z, y4.w);
        }
#pragma unroll
        for (int k = 0; k < 8; k++) {
            float4 w4 = *(const float4*)&sW[((o0 + k) << 7) + h];
            u64 w0 = pack2(w4.x, w4.x);
            u64 w1 = pack2(w4.y, w4.y);
            u64 w2 = pack2(w4.z, w4.z);
            u64 w3 = pack2(w4.w, w4.w);
            acc[k][0] = fma2(w0, ylo[0], acc[k][0]);
            acc[k][1] = fma2(w0, yhi[0], acc[k][1]);
            acc[k][0] = fma2(w1, ylo[1], acc[k][0]);
            acc[k][1] = fma2(w1, yhi[1], acc[k][1]);
            acc[k][0] = fma2(w2, ylo[2], acc[k][0]);
            acc[k][1] = fma2(w2, yhi[2], acc[k][1]);
            acc[k][0] = fma2(w3, ylo[3], acc[k][0]);
            acc[k][1] = fma2(w3, yhi[3], acc[k][1]);
        }
    }
#pragma unroll
    for (int k = 0; k < 8; k++) {
        unpack2(acc[k][0], out[k][0], out[k][1]);
        unpack2(acc[k][1], out[k][2], out[k][3]);
    }
}

#define GLU_SMEM_FLOATS (16384 + 16384 + 2048 + 2048 + 256 + 512)
__global__ void __launch_bounds__(512, 1)
glu_ln_kernel(const float* __restrict__ conv_w_l,
              const float* __restrict__ conv_b_l,
              const float* __restrict__ ln_w_l,
              const float* __restrict__ ln_b_l) {
    extern __shared__ float sm[];
    float* sW   = sm;                  // 16384 : current weight half [o][h]
    float* sY   = sm + 16384;          // 16384 : y tile [h][p]
    float* sSum = sm + 32768;          // 2048  : [warp][p]
    float* sSq  = sm + 34816;          // 2048
    float* sBias = sm + 36864;         // 256
    float* sLnw = sm + 37120;          // 128
    float* sLnb = sm + 37248;          // 128
    float* sMu  = sm + 37376;          // 128
    float* sRs  = sm + 37504;          // 128

    int t = threadIdx.x;               // 512
    int b = blockIdx.x >> 5;
    int l0 = (blockIdx.x & 31) << 7;   // 128 positions
    int ubase = b * H_ * L_;

    for (int i = t; i < 16384; i += 512) sW[i] = conv_w_l[i];
    for (int i = t; i < 16384; i += 512) {
        int h = i >> 7, p = i & 127;
        sY[i] = g_y[ubase + (h << 12) + l0 + p];
    }
    if (t < 256) sBias[t] = conv_b_l[t];
    if (t < 128) { sLnw[t] = ln_w_l[t]; sLnb[t] = ln_b_l[t]; }
    __syncthreads();

    int w = t >> 5, lane = t & 31;
    int p0 = lane << 2;
    int o0 = w << 3;

    // ---- pass A: a = Wa @ y + ba (kept in registers) ----
    float av[8][4];
    mm8x4(sW, sY, o0, p0, av);
#pragma unroll
    for (int k = 0; k < 8; k++) {
        float bv = sBias[o0 + k];
        av[k][0] += bv; av[k][1] += bv; av[k][2] += bv; av[k][3] += bv;
    }
    __syncthreads();

    for (int i = t; i < 16384; i += 512) sW[i] = conv_w_l[16384 + i];
    __syncthreads();

    // ---- pass B: g = Wg @ y + bg; r = a*sigmoid(g) + u ----
    float gv[8][4];
    mm8x4(sW, sY, o0, p0, gv);

    float s0 = 0.f, s1 = 0.f, s2 = 0.f, s3 = 0.f;
    float q0 = 0.f, q1 = 0.f, q2 = 0.f, q3 = 0.f;
#pragma unroll
    for (int k = 0; k < 8; k++) {
        float bg = sBias[128 + o0 + k];
        float4 uv = *(const float4*)&g_u[ubase + ((o0 + k) << 12) + l0 + p0];
        float r0 = fmaf(av[k][0], sigmoidf_(gv[k][0] + bg), uv.x);
        float r1 = fmaf(av[k][1], sigmoidf_(gv[k][1] + bg), uv.y);
        float r2 = fmaf(av[k][2], sigmoidf_(gv[k][2] + bg), uv.z);
        float r3 = fmaf(av[k][3], sigmoidf_(gv[k][3] + bg), uv.w);
        av[k][0] = r0; av[k][1] = r1; av[k][2] = r2; av[k][3] = r3;
        s0 += r0; s1 += r1; s2 += r2; s3 += r3;
        q0 = fmaf(r0, r0, q0); q1 = fmaf(r1, r1, q1);
        q2 = fmaf(r2, r2, q2); q3 = fmaf(r3, r3, q3);
    }
    *(float4*)&sSum[(w << 7) + p0] = make_float4(s0, s1, s2, s3);
    *(float4*)&sSq[(w << 7) + p0]  = make_float4(q0, q1, q2, q3);
    __syncthreads();

    if (t < 128) {
        float S = 0.f, Q = 0.f;
#pragma unroll
        for (int ww = 0; ww < 16; ww++) {
            S += sSum[(ww << 7) + t];
            Q += sSq[(ww << 7) + t];
        }
        float mu = S * (1.0f / H_);
        float var = Q * (1.0f / H_) - mu * mu;
        sMu[t] = mu;
        sRs[t] = rsqrtf(var + 1e-5f);
    }
    __syncthreads();

    float4 mu4 = *(const float4*)&sMu[p0];
    float4 rs4 = *(const float4*)&sRs[p0];
#pragma unroll
    for (int k = 0; k < 8; k++) {
        float lw = sLnw[o0 + k], lb = sLnb[o0 + k];
        float4 o;
        o.x = (av[k][0] - mu4.x) * rs4.x * lw + lb;
        o.y = (av[k][1] - mu4.y) * rs4.y * lw + lb;
        o.z = (av[k][2] - mu4.z) * rs4.z * lw + lb;
        o.w = (av[k][3] - mu4.w) * rs4.w * lw + lb;
        *(float4*)&g_u[ubase + ((o0 + k) << 12) + l0 + p0] = o;
    }
}

// ---------------- kernel 4: mean-pool over L --------------------------------
__global__ void pool_kernel() {
    __shared__ float red[256];
    int t = threadIdx.x;
    const float* p = g_u + (size_t)blockIdx.x * L_;
    float s = 0.f;
    for (int i = t; i < L_; i += 256) s += p[i];
    red[t] = s;
    __syncthreads();
    for (int k = 128; k > 0; k >>= 1) {
        if (t < k) red[t] += red[t + k];
        __syncthreads();
    }
    if (t == 0) g_pool[blockIdx.x] = red[0] * (1.0f / L_);
}

// ---------------- kernel 5: decoder -----------------------------------------
__global__ void decode_kernel(const float* __restrict__ dec_w,
                              const float* __restrict__ dec_b,
                              float* __restrict__ pred) {
    int t = threadIdx.x;
    if (t >= B_ * DOUT) return;
    int b = t >> 3, o = t & 7;
    float acc = dec_b[o];
    for (int h = 0; h < H_; h++)
        acc = fmaf(dec_w[o * H_ + h], g_pool[b * H_ + h], acc);
    pred[t] = 1.0f / (1.0f + expf(-acc));
}

// ---------------- kernel 6: transpose (b,h,l) -> emb (b,l,h) -----------------
__global__ void transpose_kernel(float* __restrict__ emb) {
    __shared__ float tile[32][33];
    int b = blockIdx.z;
    int h0 = blockIdx.y * 32;
    int l0 = blockIdx.x * 32;
    int tx = threadIdx.x, ty = threadIdx.y;
#pragma unroll
    for (int i = 0; i < 32; i += 8)
        tile[ty + i][tx] = g_u[((b * H_ + h0 + ty + i) << 12) + l0 + tx];
    __syncthreads();
#pragma unroll
    for (int i = 0; i < 32; i += 8)
        emb[((size_t)(b * L_ + l0 + ty + i)) * H_ + h0 + tx] = tile[tx][ty + i];
}

// ---------------- launch ------------------------------------------------------
extern "C" void kernel_launch(void* const* d_in, const int* in_sizes, int n_in,
                              void* d_out, int out_size) {
    const float* x          = (const float*)d_in[0];
    // d_in[1] = times (unused)
    const float* enc_w      = (const float*)d_in[2];
    const float* enc_b      = (const float*)d_in[3];
    const float* log_dt     = (const float*)d_in[4];
    const float* log_A_real = (const float*)d_in[5];
    const float* A_imag     = (const float*)d_in[6];
    const float* C_re       = (const float*)d_in[7];
    const float* C_im       = (const float*)d_in[8];
    const float* Dskip      = (const float*)d_in[9];
    const float* conv_w     = (const float*)d_in[10];
    const float* conv_b     = (const float*)d_in[11];
    const float* ln_w       = (const float*)d_in[12];
    const float* ln_b       = (const float*)d_in[13];
    const float* dec_w      = (const float*)d_in[14];
    const float* dec_b      = (const float*)d_in[15];

    float* out = (float*)d_out;
    float* pred = out;           // (B, DOUT) = 256 floats
    float* emb  = out + B_ * DOUT;

    static const size_t glu_smem = GLU_SMEM_FLOATS * sizeof(float);
    cudaFuncSetAttribute(glu_ln_kernel,
                         cudaFuncAttributeMaxDynamicSharedMemorySize,
                         (int)glu_smem);

    precompute_kernel<<<(NL_ * H_ * N2_ + 255) / 256, 256>>>(
        log_dt, log_A_real, A_imag, C_re, C_im);

    encoder_kernel<<<dim3(L_ / 64, B_), 256>>>(x, enc_w, enc_b);

    for (int l = 0; l < NL_; l++) {
        scan_kernel<<<256, 128>>>(l, Dskip + l * H_);
        glu_ln_kernel<<<B_ * (L_ / 128), 512, glu_smem>>>(
            conv_w + (size_t)l * 2 * H_ * H_,
            conv_b + (size_t)l * 2 * H_,
            ln_w + (size_t)l * H_,
            ln_b + (size_t)l * H_);
    }

    pool_kernel<<<B_ * H_, 256>>>();
    decode_kernel<<<1, 256>>>(dec_w, dec_b, pred);
    transpose_kernel<<<dim3(L_ / 32, H_ / 32, B_), dim3(32, 8)>>>(emb);
}

// round 7
// speedup vs baseline: 1.5810x; 1.1740x over previous
#include <cuda_runtime.h>
#include <math.h>

// Problem dims
#define B_   32
#define L_   4096
#define DIN  16
#define H_   128
#define N2_  32
#define NL_  4
#define DOUT 8

// ---------------- scratch (device globals; no allocations allowed) ----------
__device__ float g_u[B_ * H_ * L_];       // running activation, (b,h,l)
__device__ float g_y[B_ * H_ * L_];       // conv+gelu output, (b,h,l)
__device__ float g_wre[NL_ * H_ * N2_];
__device__ float g_wim[NL_ * H_ * N2_];
__device__ float g_c1[NL_ * H_ * N2_];
__device__ float g_c2[NL_ * H_ * N2_];
__device__ float g_pool[B_ * H_];

typedef unsigned long long u64;

// ---------------- f32x2 packed FMA helpers (Blackwell FFMA2) ----------------
__device__ __forceinline__ u64 pack2(float a, float b) {
    u64 r;
    asm("mov.b64 %0, {%1,%2};" : "=l"(r) : "f"(a), "f"(b));
    return r;
}
__device__ __forceinline__ void unpack2(u64 v, float& a, float& b) {
    asm("mov.b64 {%0,%1}, %2;" : "=f"(a), "=f"(b) : "l"(v));
}
__device__ __forceinline__ u64 fma2(u64 a, u64 b, u64 c) {
    u64 d;
    asm("fma.rn.f32x2 %0, %1, %2, %3;" : "=l"(d) : "l"(a), "l"(b), "l"(c));
    return d;
}

__device__ __forceinline__ float sigmoidf_(float x) {
    return 1.0f / (1.0f + expf(-x));
}

// ---------------- kernel 0: precompute SSM coefficients ---------------------
__global__ void precompute_kernel(const float* __restrict__ log_dt,
                                  const float* __restrict__ log_A_real,
                                  const float* __restrict__ A_imag,
                                  const float* __restrict__ C_re,
                                  const float* __restrict__ C_im) {
    int idx = blockIdx.x * blockDim.x + threadIdx.x;   // NL*H*N2 = 16384
    if (idx >= NL_ * H_ * N2_) return;
    int l = idx / (H_ * N2_);
    int h = (idx / N2_) % H_;

    float dt  = expf(log_dt[l * H_ + h]);
    float are = -expf(log_A_real[idx]);
    float aim = A_imag[idx];
    float dre = dt * are;
    float dim = dt * aim;
    float m   = expf(dre);
    float wre = m * cosf(dim);
    float wim = m * sinf(dim);
    // (w - 1) / A
    float nre = wre - 1.0f, nim = wim;
    float den = are * are + aim * aim;
    float inv = 1.0f / den;
    float qre = (nre * are + nim * aim) * inv;
    float qim = (nim * are - nre * aim) * inv;
    float cre = C_re[idx], cim = C_im[idx];
    float tre = cre * qre - cim * qim;
    float tim = cre * qim + cim * qre;
    g_wre[idx] = wre;
    g_wim[idx] = wim;
    g_c1[idx]  = 2.0f * tre;
    g_c2[idx]  = -2.0f * tim;
}

// ---------------- kernel 1: encoder  u[b,h,l] = x[b,l,:]·enc_w[h,:] + b -----
__global__ void encoder_kernel(const float* __restrict__ x,
                               const float* __restrict__ enc_w,
                               const float* __restrict__ enc_b) {
    __shared__ float sx[64 * 17];   // [p][d], padded
    __shared__ float sw[H_ * DIN];
    __shared__ float sb[H_];
    int t = threadIdx.x;            // 256
    int b = blockIdx.y;
    int l0 = blockIdx.x * 64;

    const float* xb = x + ((size_t)b * L_ + l0) * DIN;
    for (int i = t; i < 64 * DIN; i += 256) {
        int p = i >> 4, d = i & 15;
        sx[p * 17 + d] = xb[i];
    }
    for (int i = t; i < H_ * DIN; i += 256) sw[i] = enc_w[i];
    if (t < H_) sb[t] = enc_b[t];
    __syncthreads();

    int ubase = b * H_ * L_;
    for (int i = t; i < H_ * 64; i += 256) {
        int h = i >> 6, p = i & 63;
        float acc = sb[h];
#pragma unroll
        for (int d = 0; d < DIN; d++)
            acc = fmaf(sw[(h << 4) + d], sx[p * 17 + d], acc);
        g_u[ubase + (h << 12) + l0 + p] = acc;
    }
}

// ---------------- kernel 2: SSM scan + D skip + GELU (deferred reduction) ---
// 8 lanes per sequence, 4 complex states per lane (2 f32x2 pairs), 4 seqs/warp.
// Per-step dot products accumulate per-lane; cross-lane reduce once per 8 steps
// via recursive halving (keeps shuffles off the recurrence critical path).
__global__ void scan_kernel(int layer, const float* __restrict__ Dl) {
    const unsigned F = 0xffffffffu;
    const u64 Z0 = 0ull;
    int t = threadIdx.x;                    // 128
    int warpId = blockIdx.x * 4 + (t >> 5); // 0..1023
    int lane = t & 31;
    int lane8 = lane & 7;
    int g = lane >> 3;
    int seq = warpId * 4 + g;               // 0 .. B*H-1
    int h = seq & (H_ - 1);

    const float* z = g_u + (size_t)seq * L_;
    float* yo = g_y + (size_t)seq * L_;

    int cb = layer * (H_ * N2_) + h * N2_ + lane8 * 4;
    u64 wreA = pack2(g_wre[cb + 0], g_wre[cb + 1]);
    u64 wreB = pack2(g_wre[cb + 2], g_wre[cb + 3]);
    u64 wimA = pack2(g_wim[cb + 0], g_wim[cb + 1]);
    u64 wimB = pack2(g_wim[cb + 2], g_wim[cb + 3]);
    u64 nwimA = pack2(-g_wim[cb + 0], -g_wim[cb + 1]);
    u64 nwimB = pack2(-g_wim[cb + 2], -g_wim[cb + 3]);
    u64 c1A = pack2(g_c1[cb + 0], g_c1[cb + 1]);
    u64 c1B = pack2(g_c1[cb + 2], g_c1[cb + 3]);
    u64 c2A = pack2(g_c2[cb + 0], g_c2[cb + 1]);
    u64 c2B = pack2(g_c2[cb + 2], g_c2[cb + 3]);
    float Dh = Dl[h];

    u64 sreA = Z0, simA = Z0, sreB = Z0, simB = Z0;
    int srcb = lane & 24;
    bool b4 = (lane8 & 4) != 0;
    bool b2 = (lane8 & 2) != 0;
    bool b1 = (lane8 & 1) != 0;

    float zb = z[lane8];

    for (int t0 = 0; t0 < L_; t0 += 8) {
        int tn = (t0 + 8 < L_) ? (t0 + 8) : t0;
        float znext = z[tn + lane8];

        u64 a[8];
#pragma unroll
        for (int j = 0; j < 8; j++) {
            float zj = __shfl_sync(F, zb, srcb + j);
            u64 z2 = pack2(zj, zj);
            u64 nreA = fma2(wreA, sreA, fma2(nwimA, simA, z2));
            u64 nimA = fma2(wreA, simA, fma2(wimA, sreA, Z0));
            u64 nreB = fma2(wreB, sreB, fma2(nwimB, simB, z2));
            u64 nimB = fma2(wreB, simB, fma2(wimB, sreB, Z0));
            sreA = nreA; simA = nimA; sreB = nreB; simB = nimB;
            a[j] = fma2(c1A, sreA,
                   fma2(c2A, simA,
                   fma2(c1B, sreB,
                   fma2(c2B, simB, Z0))));
        }

        // fold f32x2 halves
        float s[8];
#pragma unroll
        for (int j = 0; j < 8; j++) {
            float lo, hi;
            unpack2(a[j], lo, hi);
            s[j] = lo + hi;
        }
        // recursive-halving reduce-scatter across the 8 lanes of the group:
        // after 3 rounds, lane j holds sum over lanes of s[j].
#pragma unroll
        for (int r = 0; r < 4; r++) {
            float send = b4 ? s[r] : s[r + 4];
            float recv = __shfl_xor_sync(F, send, 4);
            s[r] = (b4 ? s[r + 4] : s[r]) + recv;
        }
#pragma unroll
        for (int r = 0; r < 2; r++) {
            float send = b2 ? s[r] : s[r + 2];
            float recv = __shfl_xor_sync(F, send, 2);
            s[r] = (b2 ? s[r + 2] : s[r]) + recv;
        }
        {
            float send = b1 ? s[0] : s[1];
            float recv = __shfl_xor_sync(F, send, 1);
            s[0] = (b1 ? s[1] : s[0]) + recv;
        }

        float yraw = fmaf(Dh, zb, s[0]);      // zb = z[t0 + lane8]
        float gv = 0.5f * yraw * (1.0f + erff(yraw * 0.7071067811865475f));
        yo[t0 + lane8] = gv;
        zb = znext;
    }
}

// ---------------- kernel 3: fused 1x1 conv (both halves) -> GLU -> LN -------
// 512 threads; warp w computes rows o0=w*16..+15 of the 256x128 [Wa;Wg] GEMM
// for 128 positions (4/lane). Results overwrite the weight smem region.
// Epilogue: GLU + residual + LayerNorm with r-values in registers.
#define GLU_SMEM_FLOATS (32768 + 16384 + 1024 + 256 + 512)
__global__ void __launch_bounds__(512, 1)
glu_ln_kernel(const float* __restrict__ conv_w_l,
              const float* __restrict__ conv_b_l,
              const float* __restrict__ ln_w_l,
              const float* __restrict__ ln_b_l) {
    extern __shared__ float sm[];
    float* sW    = sm;                 // 32768 : [o][h] weights, later results
    float* sY    = sm + 32768;         // 16384 : y tile [h][p]
    float* sPS   = sm + 49152;         // 512   : LN partial sums [og][p]
    float* sPQ   = sm + 49664;         // 512
    float* sBias = sm + 50176;         // 256
    float* sLnw  = sm + 50432;         // 128
    float* sLnb  = sm + 50560;         // 128
    float* sMu   = sm + 50688;         // 128
    float* sRs   = sm + 50816;         // 128

    int t = threadIdx.x;               // 512
    int b = blockIdx.x >> 5;
    int l0 = (blockIdx.x & 31) << 7;   // 128 positions
    int ubase = b * H_ * L_;

    for (int i = t; i < 32768; i += 512) sW[i] = conv_w_l[i];
    for (int i = t; i < 16384; i += 512) {
        int h = i >> 7, p = i & 127;
        sY[i] = g_y[ubase + (h << 12) + l0 + p];
    }
    if (t < 256) sBias[t] = conv_b_l[t];
    if (t < 128) { sLnw[t] = ln_w_l[t]; sLnb[t] = ln_b_l[t]; }
    __syncthreads();

    int w = t >> 5, lane = t & 31;
    int p0 = lane << 2;
    int o0 = w << 4;                   // 16 rows per warp, rows 0..255

    u64 acc[16][2];
#pragma unroll
    for (int k = 0; k < 16; k++) { acc[k][0] = 0ull; acc[k][1] = 0ull; }

    for (int h = 0; h < H_; h += 4) {
        u64 ylo[4], yhi[4];
#pragma unroll
        for (int i = 0; i < 4; i++) {
            float4 y4 = *(const float4*)&sY[((h + i) << 7) + p0];
            ylo[i] = pack2(y4.x, y4.y);
            yhi[i] = pack2(y4.z, y4.w);
        }
#pragma unroll
        for (int k = 0; k < 16; k++) {
            float4 w4 = *(const float4*)&sW[((o0 + k) << 7) + h];
            u64 w0 = pack2(w4.x, w4.x);
            u64 w1 = pack2(w4.y, w4.y);
            u64 w2 = pack2(w4.z, w4.z);
            u64 w3 = pack2(w4.w, w4.w);
            acc[k][0] = fma2(w0, ylo[0], acc[k][0]);
            acc[k][1] = fma2(w0, yhi[0], acc[k][1]);
            acc[k][0] = fma2(w1, ylo[1], acc[k][0]);
            acc[k][1] = fma2(w1, yhi[1], acc[k][1]);
            acc[k][0] = fma2(w2, ylo[2], acc[k][0]);
            acc[k][1] = fma2(w2, yhi[2], acc[k][1]);
            acc[k][0] = fma2(w3, ylo[3], acc[k][0]);
            acc[k][1] = fma2(w3, yhi[3], acc[k][1]);
        }
    }

    // each warp writes ONLY its own rows -> no sync needed before overwrite
#pragma unroll
    for (int k = 0; k < 16; k++) {
        float a0, a1, a2, a3;
        unpack2(acc[k][0], a0, a1);
        unpack2(acc[k][1], a2, a3);
        float bv = sBias[o0 + k];
        float4 v = make_float4(a0 + bv, a1 + bv, a2 + bv, a3 + bv);
        *(float4*)&sW[((o0 + k) << 7) + p0] = v;
    }
    __syncthreads();

    // ---- epilogue: GLU + residual; r stays in registers ----
    int p = t & 127, og = t >> 7;      // og in 0..3, 32 channels each
    int obase = og << 5;
    float r[32];
    float s = 0.f, q = 0.f;
#pragma unroll
    for (int i = 0; i < 32; i++) {
        int o = obase + i;
        float av = sW[(o << 7) + p];
        float gv = sW[((o + 128) << 7) + p];
        float uu = g_u[ubase + (o << 12) + l0 + p];
        float rv = fmaf(av, sigmoidf_(gv), uu);
        r[i] = rv;
        s += rv;
        q = fmaf(rv, rv, q);
    }
    sPS[(og << 7) + p] = s;
    sPQ[(og << 7) + p] = q;
    __syncthreads();

    if (t < 128) {
        float S = sPS[t] + sPS[128 + t] + sPS[256 + t] + sPS[384 + t];
        float Q = sPQ[t] + sPQ[128 + t] + sPQ[256 + t] + sPQ[384 + t];
        float mu = S * (1.0f / H_);
        float var = Q * (1.0f / H_) - mu * mu;
        sMu[t] = mu;
        sRs[t] = rsqrtf(var + 1e-5f);
    }
    __syncthreads();

    float mu = sMu[p], rs = sRs[p];
#pragma unroll
    for (int i = 0; i < 32; i++) {
        int o = obase + i;
        g_u[ubase + (o << 12) + l0 + p] =
            (r[i] - mu) * rs * sLnw[o] + sLnb[o];
    }
}

// ---------------- kernel 4: mean-pool over L --------------------------------
__global__ void pool_kernel() {
    __shared__ float red[256];
    int t = threadIdx.x;
    const float* p = g_u + (size_t)blockIdx.x * L_;
    float s = 0.f;
    for (int i = t; i < L_; i += 256) s += p[i];
    red[t] = s;
    __syncthreads();
    for (int k = 128; k > 0; k >>= 1) {
        if (t < k) red[t] += red[t + k];
        __syncthreads();
    }
    if (t == 0) g_pool[blockIdx.x] = red[0] * (1.0f / L_);
}

// ---------------- kernel 5: decoder -----------------------------------------
__global__ void decode_kernel(const float* __restrict__ dec_w,
                              const float* __restrict__ dec_b,
                              float* __restrict__ pred) {
    int t = threadIdx.x;
    if (t >= B_ * DOUT) return;
    int b = t >> 3, o = t & 7;
    float acc = dec_b[o];
    for (int h = 0; h < H_; h++)
        acc = fmaf(dec_w[o * H_ + h], g_pool[b * H_ + h], acc);
    pred[t] = 1.0f / (1.0f + expf(-acc));
}

// ---------------- kernel 6: transpose (b,h,l) -> emb (b,l,h) -----------------
__global__ void transpose_kernel(float* __restrict__ emb) {
    __shared__ float tile[32][33];
    int b = blockIdx.z;
    int h0 = blockIdx.y * 32;
    int l0 = blockIdx.x * 32;
    int tx = threadIdx.x, ty = threadIdx.y;
#pragma unroll
    for (int i = 0; i < 32; i += 8)
        tile[ty + i][tx] = g_u[((b * H_ + h0 + ty + i) << 12) + l0 + tx];
    __syncthreads();
#pragma unroll
    for (int i = 0; i < 32; i += 8)
        emb[((size_t)(b * L_ + l0 + ty + i)) * H_ + h0 + tx] = tile[tx][ty + i];
}

// ---------------- launch ------------------------------------------------------
extern "C" void kernel_launch(void* const* d_in, const int* in_sizes, int n_in,
                              void* d_out, int out_size) {
    const float* x          = (const float*)d_in[0];
    // d_in[1] = times (unused)
    const float* enc_w      = (const float*)d_in[2];
    const float* enc_b      = (const float*)d_in[3];
    const float* log_dt     = (const float*)d_in[4];
    const float* log_A_real = (const float*)d_in[5];
    const float* A_imag     = (const float*)d_in[6];
    const float* C_re       = (const float*)d_in[7];
    const float* C_im       = (const float*)d_in[8];
    const float* Dskip      = (const float*)d_in[9];
    const float* conv_w     = (const float*)d_in[10];
    const float* conv_b     = (const float*)d_in[11];
    const float* ln_w       = (const float*)d_in[12];
    const float* ln_b       = (const float*)d_in[13];
    const float* dec_w      = (const float*)d_in[14];
    const float* dec_b      = (const float*)d_in[15];

    float* out = (float*)d_out;
    float* pred = out;           // (B, DOUT) = 256 floats
    float* emb  = out + B_ * DOUT;

    static const size_t glu_smem = GLU_SMEM_FLOATS * sizeof(float);
    cudaFuncSetAttribute(glu_ln_kernel,
                         cudaFuncAttributeMaxDynamicSharedMemorySize,
                         (int)glu_smem);

    precompute_kernel<<<(NL_ * H_ * N2_ + 255) / 256, 256>>>(
        log_dt, log_A_real, A_imag, C_re, C_im);

    encoder_kernel<<<dim3(L_ / 64, B_), 256>>>(x, enc_w, enc_b);

    for (int l = 0; l < NL_; l++) {
        scan_kernel<<<256, 128>>>(l, Dskip + l * H_);
        glu_ln_kernel<<<B_ * (L_ / 128), 512, glu_smem>>>(
            conv_w + (size_t)l * 2 * H_ * H_,
            conv_b + (size_t)l * 2 * H_,
            ln_w + (size_t)l * H_,
            ln_b + (size_t)l * H_);
    }

    pool_kernel<<<B_ * H_, 256>>>();
    decode_kernel<<<1, 256>>>(dec_w, dec_b, pred);
    transpose_kernel<<<dim3(L_ / 32, H_ / 32, B_), dim3(32, 8)>>>(emb);
}

// round 8
// speedup vs baseline: 1.7531x; 1.1089x over previous
#include <cuda_runtime.h>
#include <math.h>

// Problem dims
#define B_   32
#define L_   4096
#define DIN  16
#define H_   128
#define N2_  32
#define NL_  4
#define DOUT 8

// ---------------- scratch (device globals; no allocations allowed) ----------
__device__ float g_u[B_ * H_ * L_];       // running activation, (b,h,l)
__device__ float g_y[B_ * H_ * L_];       // conv+gelu output, (b,h,l)
__device__ float g_wre[NL_ * H_ * N2_];
__device__ float g_wim[NL_ * H_ * N2_];
__device__ float g_c1[NL_ * H_ * N2_];
__device__ float g_c2[NL_ * H_ * N2_];
__device__ float g_pool[B_ * H_];

typedef unsigned long long u64;

// ---------------- f32x2 packed FMA helpers (Blackwell FFMA2) ----------------
__device__ __forceinline__ u64 pack2(float a, float b) {
    u64 r;
    asm("mov.b64 %0, {%1,%2};" : "=l"(r) : "f"(a), "f"(b));
    return r;
}
__device__ __forceinline__ void unpack2(u64 v, float& a, float& b) {
    asm("mov.b64 {%0,%1}, %2;" : "=f"(a), "=f"(b) : "l"(v));
}
__device__ __forceinline__ u64 fma2(u64 a, u64 b, u64 c) {
    u64 d;
    asm("fma.rn.f32x2 %0, %1, %2, %3;" : "=l"(d) : "l"(a), "l"(b), "l"(c));
    return d;
}

__device__ __forceinline__ float sigmoidf_(float x) {
    return 1.0f / (1.0f + expf(-x));
}

// ---------------- kernel 0: precompute SSM coefficients ---------------------
__global__ void precompute_kernel(const float* __restrict__ log_dt,
                                  const float* __restrict__ log_A_real,
                                  const float* __restrict__ A_imag,
                                  const float* __restrict__ C_re,
                                  const float* __restrict__ C_im) {
    int idx = blockIdx.x * blockDim.x + threadIdx.x;   // NL*H*N2 = 16384
    if (idx >= NL_ * H_ * N2_) return;
    int l = idx / (H_ * N2_);
    int h = (idx / N2_) % H_;

    float dt  = expf(log_dt[l * H_ + h]);
    float are = -expf(log_A_real[idx]);
    float aim = A_imag[idx];
    float dre = dt * are;
    float dim = dt * aim;
    float m   = expf(dre);
    float wre = m * cosf(dim);
    float wim = m * sinf(dim);
    // (w - 1) / A
    float nre = wre - 1.0f, nim = wim;
    float den = are * are + aim * aim;
    float inv = 1.0f / den;
    float qre = (nre * are + nim * aim) * inv;
    float qim = (nim * are - nre * aim) * inv;
    float cre = C_re[idx], cim = C_im[idx];
    float tre = cre * qre - cim * qim;
    float tim = cre * qim + cim * qre;
    g_wre[idx] = wre;
    g_wim[idx] = wim;
    g_c1[idx]  = 2.0f * tre;
    g_c2[idx]  = -2.0f * tim;
}

// ---------------- kernel 1: encoder  u[b,h,l] = x[b,l,:]·enc_w[h,:] + b -----
__global__ void encoder_kernel(const float* __restrict__ x,
                               const float* __restrict__ enc_w,
                               const float* __restrict__ enc_b) {
    __shared__ float sx[64 * 17];   // [p][d], padded
    __shared__ float sw[H_ * DIN];
    __shared__ float sb[H_];
    int t = threadIdx.x;            // 256
    int b = blockIdx.y;
    int l0 = blockIdx.x * 64;

    const float* xb = x + ((size_t)b * L_ + l0) * DIN;
    for (int i = t; i < 64 * DIN; i += 256) {
        int p = i >> 4, d = i & 15;
        sx[p * 17 + d] = xb[i];
    }
    for (int i = t; i < H_ * DIN; i += 256) sw[i] = enc_w[i];
    if (t < H_) sb[t] = enc_b[t];
    __syncthreads();

    int ubase = b * H_ * L_;
    for (int i = t; i < H_ * 64; i += 256) {
        int h = i >> 6, p = i & 63;
        float acc = sb[h];
#pragma unroll
        for (int d = 0; d < DIN; d++)
            acc = fmaf(sw[(h << 4) + d], sx[p * 17 + d], acc);
        g_u[ubase + (h << 12) + l0 + p] = acc;
    }
}

// ---------------- kernel 2: SSM scan + D skip + GELU ------------------------
// 16 lanes per sequence, 2 complex states per lane (one f32x2 pair),
// 2 sequences per warp -> 2048 warps. 32-step blocks with float2 z loads,
// deferred reduce-scatter (lane l ends with timesteps 2l, 2l+1).
__global__ void __launch_bounds__(128)
scan_kernel(int layer, const float* __restrict__ Dl) {
    const unsigned F = 0xffffffffu;
    const u64 Z0 = 0ull;
    int t = threadIdx.x;                    // 128
    int warpId = blockIdx.x * 4 + (t >> 5); // 0..2047
    int lane = t & 31;
    int lane16 = lane & 15;
    int g = lane >> 4;                      // 0/1
    int seq = warpId * 2 + g;               // 0 .. B*H-1
    int h = seq & (H_ - 1);

    const float* z = g_u + (size_t)seq * L_;
    float* yo = g_y + (size_t)seq * L_;

    int cb = layer * (H_ * N2_) + h * N2_ + lane16 * 2;
    u64 wre  = pack2(g_wre[cb], g_wre[cb + 1]);
    u64 wim  = pack2(g_wim[cb], g_wim[cb + 1]);
    u64 nwim = pack2(-g_wim[cb], -g_wim[cb + 1]);
    u64 c1   = pack2(g_c1[cb], g_c1[cb + 1]);
    u64 c2   = pack2(g_c2[cb], g_c2[cb + 1]);
    float Dh = Dl[h];

    u64 sre = Z0, sim = Z0;
    int base16 = lane & 16;
    bool q8 = (lane16 & 8) != 0;
    bool q4 = (lane16 & 4) != 0;
    bool q2 = (lane16 & 2) != 0;
    bool q1 = (lane16 & 1) != 0;

    float2 zb = *(const float2*)&z[lane16 * 2];

    for (int t0 = 0; t0 < L_; t0 += 32) {
        int tn = (t0 + 32 < L_) ? t0 + 32 : t0;
        float2 zn = *(const float2*)&z[tn + lane16 * 2];

        float s[32];
#pragma unroll
        for (int j = 0; j < 32; j++) {
            float comp = (j & 1) ? zb.y : zb.x;
            float zj = __shfl_sync(F, comp, base16 + (j >> 1));
            u64 z2 = pack2(zj, zj);
            u64 nre = fma2(wre, sre, fma2(nwim, sim, z2));
            u64 nim = fma2(wre, sim, fma2(wim, sre, Z0));
            sre = nre; sim = nim;
            u64 d = fma2(c1, sre, fma2(c2, sim, Z0));
            float lo, hi;
            unpack2(d, lo, hi);
            s[j] = lo + hi;
        }
        // reduce-scatter 32 values over 16 lanes (4 rounds); lane l16 ends
        // with s[0..1] = totals for timesteps t0 + 2*l16 + {0,1}.
#pragma unroll
        for (int r = 0; r < 16; r++) {
            float send = q8 ? s[r] : s[r + 16];
            float recv = __shfl_xor_sync(F, send, 8);
            s[r] = (q8 ? s[r + 16] : s[r]) + recv;
        }
#pragma unroll
        for (int r = 0; r < 8; r++) {
            float send = q4 ? s[r] : s[r + 8];
            float recv = __shfl_xor_sync(F, send, 4);
            s[r] = (q4 ? s[r + 8] : s[r]) + recv;
        }
#pragma unroll
        for (int r = 0; r < 4; r++) {
            float send = q2 ? s[r] : s[r + 4];
            float recv = __shfl_xor_sync(F, send, 2);
            s[r] = (q2 ? s[r + 4] : s[r]) + recv;
        }
#pragma unroll
        for (int r = 0; r < 2; r++) {
            float send = q1 ? s[r] : s[r + 2];
            float recv = __shfl_xor_sync(F, send, 1);
            s[r] = (q1 ? s[r + 2] : s[r]) + recv;
        }

        float y0 = fmaf(Dh, zb.x, s[0]);
        float y1 = fmaf(Dh, zb.y, s[1]);
        float2 out;
        out.x = 0.5f * y0 * (1.0f + erff(y0 * 0.7071067811865475f));
        out.y = 0.5f * y1 * (1.0f + erff(y1 * 0.7071067811865475f));
        *(float2*)&yo[t0 + lane16 * 2] = out;
        zb = zn;
    }
}

// ---------------- kernel 3: fused 1x1 conv (both halves) -> GLU -> LN -------
// 512 threads; warp w computes rows w*16..+15 of the 256x128 [Wa;Wg] GEMM
// for 128 positions (4/lane), writes back into sW. Epilogue: fully-float4
// GLU + residual + LayerNorm; r-values stay in registers.
#define GLU_SMEM_FLOATS (32768 + 16384 + 2048 + 2048 + 256 + 512)
__global__ void __launch_bounds__(512, 1)
glu_ln_kernel(const float* __restrict__ conv_w_l,
              const float* __restrict__ conv_b_l,
              const float* __restrict__ ln_w_l,
              const float* __restrict__ ln_b_l) {
    extern __shared__ float sm[];
    float* sW    = sm;                 // 32768 : [o][h] weights, later results
    float* sY    = sm + 32768;         // 16384 : y tile [h][p]
    float* sPS   = sm + 49152;         // 2048  : LN partial sums [warp][p]
    float* sPQ   = sm + 51200;         // 2048
    float* sBias = sm + 53248;         // 256
    float* sLnw  = sm + 53504;         // 128
    float* sLnb  = sm + 53632;         // 128
    float* sMu   = sm + 53760;         // 128
    float* sRs   = sm + 53888;         // 128

    int t = threadIdx.x;               // 512
    int b = blockIdx.x >> 5;
    int l0 = (blockIdx.x & 31) << 7;   // 128 positions
    int ubase = b * H_ * L_;

    // float4 staging of weights and y tile
    for (int i = t; i < 8192; i += 512)
        *(float4*)&sW[i << 2] = *(const float4*)&conv_w_l[i << 2];
    for (int i = t; i < 4096; i += 512) {
        int h = i >> 5, p4 = i & 31;
        *(float4*)&sY[(h << 7) + (p4 << 2)] =
            *(const float4*)&g_y[ubase + (h << 12) + l0 + (p4 << 2)];
    }
    if (t < 256) sBias[t] = conv_b_l[t];
    if (t < 128) { sLnw[t] = ln_w_l[t]; sLnb[t] = ln_b_l[t]; }
    __syncthreads();

    int w = t >> 5, lane = t & 31;
    int p0 = lane << 2;
    int o0 = w << 4;                   // 16 rows per warp, rows 0..255

    u64 acc[16][2];
#pragma unroll
    for (int k = 0; k < 16; k++) { acc[k][0] = 0ull; acc[k][1] = 0ull; }

    for (int h = 0; h < H_; h += 4) {
        u64 ylo[4], yhi[4];
#pragma unroll
        for (int i = 0; i < 4; i++) {
            float4 y4 = *(const float4*)&sY[((h + i) << 7) + p0];
            ylo[i] = pack2(y4.x, y4.y);
            yhi[i] = pack2(y4.z, y4.w);
        }
#pragma unroll
        for (int k = 0; k < 16; k++) {
            float4 w4 = *(const float4*)&sW[((o0 + k) << 7) + h];
            u64 w0 = pack2(w4.x, w4.x);
            u64 w1 = pack2(w4.y, w4.y);
            u64 w2 = pack2(w4.z, w4.z);
            u64 w3 = pack2(w4.w, w4.w);
            acc[k][0] = fma2(w0, ylo[0], acc[k][0]);
            acc[k][1] = fma2(w0, yhi[0], acc[k][1]);
            acc[k][0] = fma2(w1, ylo[1], acc[k][0]);
            acc[k][1] = fma2(w1, yhi[1], acc[k][1]);
            acc[k][0] = fma2(w2, ylo[2], acc[k][0]);
            acc[k][1] = fma2(w2, yhi[2], acc[k][1]);
            acc[k][0] = fma2(w3, ylo[3], acc[k][0]);
            acc[k][1] = fma2(w3, yhi[3], acc[k][1]);
        }
    }

    // each warp writes ONLY its own rows -> no sync needed before overwrite
#pragma unroll
    for (int k = 0; k < 16; k++) {
        float a0, a1, a2, a3;
        unpack2(acc[k][0], a0, a1);
        unpack2(acc[k][1], a2, a3);
        float bv = sBias[o0 + k];
        float4 v = make_float4(a0 + bv, a1 + bv, a2 + bv, a3 + bv);
        *(float4*)&sW[((o0 + k) << 7) + p0] = v;
    }
    __syncthreads();

    // ---- epilogue: float4 GLU + residual; r stays in registers ----
    int oe = w << 3;                   // 8 channels per warp (0..127)
    float4 r[8];
    float4 s4 = make_float4(0.f, 0.f, 0.f, 0.f);
    float4 q4 = make_float4(0.f, 0.f, 0.f, 0.f);
#pragma unroll
    for (int k = 0; k < 8; k++) {
        int o = oe + k;
        float4 a4 = *(const float4*)&sW[(o << 7) + p0];
        float4 g4 = *(const float4*)&sW[((o + 128) << 7) + p0];
        float4 u4 = *(const float4*)&g_u[ubase + (o << 12) + l0 + p0];
        r[k].x = fmaf(a4.x, sigmoidf_(g4.x), u4.x);
        r[k].y = fmaf(a4.y, sigmoidf_(g4.y), u4.y);
        r[k].z = fmaf(a4.z, sigmoidf_(g4.z), u4.z);
        r[k].w = fmaf(a4.w, sigmoidf_(g4.w), u4.w);
        s4.x += r[k].x; s4.y += r[k].y; s4.z += r[k].z; s4.w += r[k].w;
        q4.x = fmaf(r[k].x, r[k].x, q4.x);
        q4.y = fmaf(r[k].y, r[k].y, q4.y);
        q4.z = fmaf(r[k].z, r[k].z, q4.z);
        q4.w = fmaf(r[k].w, r[k].w, q4.w);
    }
    *(float4*)&sPS[(w << 7) + p0] = s4;
    *(float4*)&sPQ[(w << 7) + p0] = q4;
    __syncthreads();

    if (t < 128) {
        float S = 0.f, Q = 0.f;
#pragma unroll
        for (int ww = 0; ww < 16; ww++) {
            S += sPS[(ww << 7) + t];
            Q += sPQ[(ww << 7) + t];
        }
        float mu = S * (1.0f / H_);
        float var = Q * (1.0f / H_) - mu * mu;
        sMu[t] = mu;
        sRs[t] = rsqrtf(var + 1e-5f);
    }
    __syncthreads();

    float4 mu4 = *(const float4*)&sMu[p0];
    float4 rs4 = *(const float4*)&sRs[p0];
#pragma unroll
    for (int k = 0; k < 8; k++) {
        int o = oe + k;
        float lw = sLnw[o], lb = sLnb[o];
        float4 v;
        v.x = (r[k].x - mu4.x) * rs4.x * lw + lb;
        v.y = (r[k].y - mu4.y) * rs4.y * lw + lb;
        v.z = (r[k].z - mu4.z) * rs4.z * lw + lb;
        v.w = (r[k].w - mu4.w) * rs4.w * lw + lb;
        *(float4*)&g_u[ubase + (o << 12) + l0 + p0] = v;
    }
}

// ---------------- kernel 4: mean-pool over L --------------------------------
__global__ void pool_kernel() {
    __shared__ float red[256];
    int t = threadIdx.x;
    const float* p = g_u + (size_t)blockIdx.x * L_;
    float s = 0.f;
    for (int i = t; i < L_; i += 256) s += p[i];
    red[t] = s;
    __syncthreads();
    for (int k = 128; k > 0; k >>= 1) {
        if (t < k) red[t] += red[t + k];
        __syncthreads();
    }
    if (t == 0) g_pool[blockIdx.x] = red[0] * (1.0f / L_);
}

// ---------------- kernel 5: decoder -----------------------------------------
__global__ void decode_kernel(const float* __restrict__ dec_w,
                              const float* __restrict__ dec_b,
                              float* __restrict__ pred) {
    int t = threadIdx.x;
    if (t >= B_ * DOUT) return;
    int b = t >> 3, o = t & 7;
    float acc = dec_b[o];
    for (int h = 0; h < H_; h++)
        acc = fmaf(dec_w[o * H_ + h], g_pool[b * H_ + h], acc);
    pred[t] = 1.0f / (1.0f + expf(-acc));
}

// ---------------- kernel 6: transpose (b,h,l) -> emb (b,l,h) -----------------
__global__ void transpose_kernel(float* __restrict__ emb) {
    __shared__ float tile[32][33];
    int b = blockIdx.z;
    int h0 = blockIdx.y * 32;
    int l0 = blockIdx.x * 32;
    int tx = threadIdx.x, ty = threadIdx.y;
#pragma unroll
    for (int i = 0; i < 32; i += 8)
        tile[ty + i][tx] = g_u[((b * H_ + h0 + ty + i) << 12) + l0 + tx];
    __syncthreads();
#pragma unroll
    for (int i = 0; i < 32; i += 8)
        emb[((size_t)(b * L_ + l0 + ty + i)) * H_ + h0 + tx] = tile[tx][ty + i];
}

// ---------------- launch ------------------------------------------------------
extern "C" void kernel_launch(void* const* d_in, const int* in_sizes, int n_in,
                              void* d_out, int out_size) {
    const float* x          = (const float*)d_in[0];
    // d_in[1] = times (unused)
    const float* enc_w      = (const float*)d_in[2];
    const float* enc_b      = (const float*)d_in[3];
    const float* log_dt     = (const float*)d_in[4];
    const float* log_A_real = (const float*)d_in[5];
    const float* A_imag     = (const float*)d_in[6];
    const float* C_re       = (const float*)d_in[7];
    const float* C_im       = (const float*)d_in[8];
    const float* Dskip      = (const float*)d_in[9];
    const float* conv_w     = (const float*)d_in[10];
    const float* conv_b     = (const float*)d_in[11];
    const float* ln_w       = (const float*)d_in[12];
    const float* ln_b       = (const float*)d_in[13];
    const float* dec_w      = (const float*)d_in[14];
    const float* dec_b      = (const float*)d_in[15];

    float* out = (float*)d_out;
    float* pred = out;           // (B, DOUT) = 256 floats
    float* emb  = out + B_ * DOUT;

    static const size_t glu_smem = GLU_SMEM_FLOATS * sizeof(float);
    cudaFuncSetAttribute(glu_ln_kernel,
                         cudaFuncAttributeMaxDynamicSharedMemorySize,
                         (int)glu_smem);

    precompute_kernel<<<(NL_ * H_ * N2_ + 255) / 256, 256>>>(
        log_dt, log_A_real, A_imag, C_re, C_im);

    encoder_kernel<<<dim3(L_ / 64, B_), 256>>>(x, enc_w, enc_b);

    for (int l = 0; l < NL_; l++) {
        scan_kernel<<<512, 128>>>(l, Dskip + l * H_);
        glu_ln_kernel<<<B_ * (L_ / 128), 512, glu_smem>>>(
            conv_w + (size_t)l * 2 * H_ * H_,
            conv_b + (size_t)l * 2 * H_,
            ln_w + (size_t)l * H_,
            ln_b + (size_t)l * H_);
    }

    pool_kernel<<<B_ * H_, 256>>>();
    decode_kernel<<<1, 256>>>(dec_w, dec_b, pred);
    transpose_kernel<<<dim3(L_ / 32, H_ / 32, B_), dim3(32, 8)>>>(emb);
}

// round 9
// speedup vs baseline: 1.9133x; 1.0914x over previous
#include <cuda_runtime.h>
#include <math.h>

// Problem dims
#define B_   32
#define L_   4096
#define DIN  16
#define H_   128
#define N2_  32
#define NL_  4
#define DOUT 8

// ---------------- scratch (device globals; no allocations allowed) ----------
__device__ float g_u[B_ * H_ * L_];       // running activation, (b,h,l)
__device__ float g_y[B_ * H_ * L_];       // conv+gelu output, (b,h,l)
__device__ float g_wre[NL_ * H_ * N2_];
__device__ float g_wim[NL_ * H_ * N2_];
__device__ float g_c1[NL_ * H_ * N2_];
__device__ float g_c2[NL_ * H_ * N2_];
__device__ float g_pool[B_ * H_];

typedef unsigned long long u64;

// ---------------- f32x2 packed FMA helpers (Blackwell FFMA2) ----------------
__device__ __forceinline__ u64 pack2(float a, float b) {
    u64 r;
    asm("mov.b64 %0, {%1,%2};" : "=l"(r) : "f"(a), "f"(b));
    return r;
}
__device__ __forceinline__ void unpack2(u64 v, float& a, float& b) {
    asm("mov.b64 {%0,%1}, %2;" : "=f"(a), "=f"(b) : "l"(v));
}
__device__ __forceinline__ u64 fma2(u64 a, u64 b, u64 c) {
    u64 d;
    asm("fma.rn.f32x2 %0, %1, %2, %3;" : "=l"(d) : "l"(a), "l"(b), "l"(c));
    return d;
}

__device__ __forceinline__ float sigmoidf_(float x) {
    return 1.0f / (1.0f + expf(-x));
}

// ---------------- kernel 0: precompute SSM coefficients ---------------------
__global__ void precompute_kernel(const float* __restrict__ log_dt,
                                  const float* __restrict__ log_A_real,
                                  const float* __restrict__ A_imag,
                                  const float* __restrict__ C_re,
                                  const float* __restrict__ C_im) {
    int idx = blockIdx.x * blockDim.x + threadIdx.x;   // NL*H*N2 = 16384
    if (idx >= NL_ * H_ * N2_) return;
    int l = idx / (H_ * N2_);
    int h = (idx / N2_) % H_;

    float dt  = expf(log_dt[l * H_ + h]);
    float are = -expf(log_A_real[idx]);
    float aim = A_imag[idx];
    float dre = dt * are;
    float dim = dt * aim;
    float m   = expf(dre);
    float wre = m * cosf(dim);
    float wim = m * sinf(dim);
    // (w - 1) / A
    float nre = wre - 1.0f, nim = wim;
    float den = are * are + aim * aim;
    float inv = 1.0f / den;
    float qre = (nre * are + nim * aim) * inv;
    float qim = (nim * are - nre * aim) * inv;
    float cre = C_re[idx], cim = C_im[idx];
    float tre = cre * qre - cim * qim;
    float tim = cre * qim + cim * qre;
    g_wre[idx] = wre;
    g_wim[idx] = wim;
    g_c1[idx]  = 2.0f * tre;
    g_c2[idx]  = -2.0f * tim;
}

// ---------------- kernel 1: encoder  u[b,h,l] = x[b,l,:]·enc_w[h,:] + b -----
__global__ void encoder_kernel(const float* __restrict__ x,
                               const float* __restrict__ enc_w,
                               const float* __restrict__ enc_b) {
    __shared__ float sx[64 * 17];   // [p][d], padded
    __shared__ float sw[H_ * DIN];
    __shared__ float sb[H_];
    int t = threadIdx.x;            // 256
    int b = blockIdx.y;
    int l0 = blockIdx.x * 64;

    const float* xb = x + ((size_t)b * L_ + l0) * DIN;
    for (int i = t; i < 64 * DIN; i += 256) {
        int p = i >> 4, d = i & 15;
        sx[p * 17 + d] = xb[i];
    }
    for (int i = t; i < H_ * DIN; i += 256) sw[i] = enc_w[i];
    if (t < H_) sb[t] = enc_b[t];
    __syncthreads();

    int ubase = b * H_ * L_;
    for (int i = t; i < H_ * 64; i += 256) {
        int h = i >> 6, p = i & 63;
        float acc = sb[h];
#pragma unroll
        for (int d = 0; d < DIN; d++)
            acc = fmaf(sw[(h << 4) + d], sx[p * 17 + d], acc);
        g_u[ubase + (h << 12) + l0 + p] = acc;
    }
}

// ---------------- kernel 2: SSM scan + D skip + GELU ------------------------
// 16 lanes per sequence, 2 complex states per lane (one f32x2 pair),
// 2 sequences per warp. z delivered via uniform-address float4 loads (L1
// broadcast) instead of shuffles; only the per-16-step reduce-scatter
// (15 shuffles) remains on the shuffle pipe.
__global__ void __launch_bounds__(128)
scan_kernel(int layer, const float* __restrict__ Dl) {
    const unsigned F = 0xffffffffu;
    const u64 Z0 = 0ull;
    int t = threadIdx.x;                    // 128
    int warpId = blockIdx.x * 4 + (t >> 5); // 0..2047
    int lane = t & 31;
    int lane16 = lane & 15;
    int g = lane >> 4;                      // 0/1
    int seq = warpId * 2 + g;               // 0 .. B*H-1
    int h = seq & (H_ - 1);

    const float* z = g_u + (size_t)seq * L_;
    float* yo = g_y + (size_t)seq * L_;

    int cb = layer * (H_ * N2_) + h * N2_ + lane16 * 2;
    u64 wre  = pack2(g_wre[cb], g_wre[cb + 1]);
    u64 wim  = pack2(g_wim[cb], g_wim[cb + 1]);
    u64 nwim = pack2(-g_wim[cb], -g_wim[cb + 1]);
    u64 d1   = pack2(g_c1[cb], g_c1[cb + 1]);
    u64 d2   = pack2(g_c2[cb], g_c2[cb + 1]);
    float Dh = Dl[h];

    u64 sre = Z0, sim = Z0;
    bool q8 = (lane16 & 8) != 0;
    bool q4 = (lane16 & 4) != 0;
    bool q2 = (lane16 & 2) != 0;
    bool q1 = (lane16 & 1) != 0;

    const float4* z4 = (const float4*)z;
    float4 c0 = z4[0], c1v = z4[1], c2v = z4[2], c3v = z4[3];

    for (int t0 = 0; t0 < L_; t0 += 16) {
        int nb = (t0 + 16 < L_) ? ((t0 + 16) >> 2) : (t0 >> 2);
        float4 n0 = z4[nb], n1 = z4[nb + 1], n2 = z4[nb + 2], n3 = z4[nb + 3];
        float zown = z[t0 + lane16];        // coalesced per half-warp

        float zc[16] = {c0.x, c0.y, c0.z, c0.w,
                        c1v.x, c1v.y, c1v.z, c1v.w,
                        c2v.x, c2v.y, c2v.z, c2v.w,
                        c3v.x, c3v.y, c3v.z, c3v.w};
        float s[16];
#pragma unroll
        for (int j = 0; j < 16; j++) {
            u64 z2 = pack2(zc[j], zc[j]);
            u64 nre = fma2(wre, sre, fma2(nwim, sim, z2));
            u64 nim = fma2(wre, sim, fma2(wim, sre, Z0));
            sre = nre; sim = nim;
            u64 d = fma2(d1, sre, fma2(d2, sim, Z0));
            float lo, hi;
            unpack2(d, lo, hi);
            s[j] = lo + hi;
        }
        // reduce-scatter 16 values over 16 lanes; lane l ends with total
        // for timestep t0 + l in s[0].
#pragma unroll
        for (int r = 0; r < 8; r++) {
            float send = q8 ? s[r] : s[r + 8];
            float recv = __shfl_xor_sync(F, send, 8);
            s[r] = (q8 ? s[r + 8] : s[r]) + recv;
        }
#pragma unroll
        for (int r = 0; r < 4; r++) {
            float send = q4 ? s[r] : s[r + 4];
            float recv = __shfl_xor_sync(F, send, 4);
            s[r] = (q4 ? s[r + 4] : s[r]) + recv;
        }
#pragma unroll
        for (int r = 0; r < 2; r++) {
            float send = q2 ? s[r] : s[r + 2];
            float recv = __shfl_xor_sync(F, send, 2);
            s[r] = (q2 ? s[r + 2] : s[r]) + recv;
        }
        {
            float send = q1 ? s[0] : s[1];
            float recv = __shfl_xor_sync(F, send, 1);
            s[0] = (q1 ? s[1] : s[0]) + recv;
        }

        float yraw = fmaf(Dh, zown, s[0]);
        float gv = 0.5f * yraw * (1.0f + erff(yraw * 0.7071067811865475f));
        yo[t0 + lane16] = gv;
        c0 = n0; c1v = n1; c2v = n2; c3v = n3;
    }
}

// ---------------- kernel 3: fused 1x1 conv (both halves) -> GLU -> LN -------
// Weights staged TRANSPOSED: sWt[h][o] (row stride 260). Accumulators pack
// over output-channel pairs -> weight pairs load directly as ulonglong2
// (lane-uniform broadcast, no splat movs); only y needs 4 splats per h.
// After GEMM, results overwrite sWt as res[o*128+p]; float4 epilogue.
#define WT_STRIDE 260
#define GLU_SMEM_FLOATS (33280 + 16384 + 2048 + 2048 + 256 + 512)
__global__ void __launch_bounds__(512, 1)
glu_ln_kernel(const float* __restrict__ conv_w_l,
              const float* __restrict__ conv_b_l,
              const float* __restrict__ ln_w_l,
              const float* __restrict__ ln_b_l) {
    extern __shared__ float sm[];
    float* sWt   = sm;                 // 128*260 : transposed weights / results
    float* sY    = sm + 33280;         // 16384 : y tile [h][p]
    float* sPS   = sm + 49664;         // 2048  : LN partial sums [warp][p]
    float* sPQ   = sm + 51712;         // 2048
    float* sBias = sm + 53760;         // 256
    float* sLnw  = sm + 54016;         // 128
    float* sLnb  = sm + 54144;         // 128
    float* sMu   = sm + 54272;         // 128
    float* sRs   = sm + 54400;         // 128

    int t = threadIdx.x;               // 512
    int b = blockIdx.x >> 5;
    int l0 = (blockIdx.x & 31) << 7;   // 128 positions
    int ubase = b * H_ * L_;

    // ---- staging: transposed weights (coalesced LDG per o-row) ----
    {
        int hh = t & 127;
        int oqb = (t >> 7) << 4;       // 0,16,32,48
#pragma unroll
        for (int k = 0; k < 16; k++) {
            int o = (oqb + k) << 2;
            float4 v;
            v.x = conv_w_l[(o + 0) * 128 + hh];
            v.y = conv_w_l[(o + 1) * 128 + hh];
            v.z = conv_w_l[(o + 2) * 128 + hh];
            v.w = conv_w_l[(o + 3) * 128 + hh];
            *(float4*)&sWt[hh * WT_STRIDE + o] = v;
        }
    }
    // ---- y tile (float4) ----
    for (int i = t; i < 4096; i += 512) {
        int hh = i >> 5, p4 = i & 31;
        *(float4*)&sY[(hh << 7) + (p4 << 2)] =
            *(const float4*)&g_y[ubase + (hh << 12) + l0 + (p4 << 2)];
    }
    if (t < 256) sBias[t] = conv_b_l[t];
    if (t < 128) { sLnw[t] = ln_w_l[t]; sLnb[t] = ln_b_l[t]; }
    __syncthreads();

    int w = t >> 5, lane = t & 31;
    int p0 = lane << 2;
    int o0 = w << 4;                   // 16 output rows per warp

    u64 acc[8][4];                     // [o-pair][position]
#pragma unroll
    for (int j = 0; j < 8; j++)
#pragma unroll
        for (int p = 0; p < 4; p++) acc[j][p] = 0ull;

#pragma unroll 2
    for (int h = 0; h < H_; h++) {
        float4 yv = *(const float4*)&sY[(h << 7) + p0];
        u64 ys0 = pack2(yv.x, yv.x);
        u64 ys1 = pack2(yv.y, yv.y);
        u64 ys2 = pack2(yv.z, yv.z);
        u64 ys3 = pack2(yv.w, yv.w);
        const float* wr = &sWt[h * WT_STRIDE + o0];
        ulonglong2 wA = *(const ulonglong2*)(wr);       // pairs 0,1
        ulonglong2 wB = *(const ulonglong2*)(wr + 4);   // pairs 2,3
        ulonglong2 wC = *(const ulonglong2*)(wr + 8);   // pairs 4,5
        ulonglong2 wD = *(const ulonglong2*)(wr + 12);  // pairs 6,7
        u64 wp[8] = {wA.x, wA.y, wB.x, wB.y, wC.x, wC.y, wD.x, wD.y};
#pragma unroll
        for (int j = 0; j < 8; j++) {
            acc[j][0] = fma2(wp[j], ys0, acc[j][0]);
            acc[j][1] = fma2(wp[j], ys1, acc[j][1]);
            acc[j][2] = fma2(wp[j], ys2, acc[j][2]);
            acc[j][3] = fma2(wp[j], ys3, acc[j][3]);
        }
    }
    __syncthreads();                   // weights dead; reuse sWt for results

    // ---- writeback + bias into res[o*128 + p] ----
#pragma unroll
    for (int j = 0; j < 8; j++) {
        int oe = o0 + 2 * j;
        float e0, f0, e1, f1, e2, f2, e3, f3;
        unpack2(acc[j][0], e0, f0);
        unpack2(acc[j][1], e1, f1);
        unpack2(acc[j][2], e2, f2);
        unpack2(acc[j][3], e3, f3);
        float be = sBias[oe], bo = sBias[oe + 1];
        float4 ve = make_float4(e0 + be, e1 + be, e2 + be, e3 + be);
        float4 vo = make_float4(f0 + bo, f1 + bo, f2 + bo, f3 + bo);
        *(float4*)&sWt[(oe << 7) + p0] = ve;
        *(float4*)&sWt[((oe + 1) << 7) + p0] = vo;
    }
    __syncthreads();

    // ---- epilogue: float4 GLU + residual; r stays in registers ----
    int oe = w << 3;                   // 8 channels per warp (0..127)
    float4 r[8];
    float4 s4 = make_float4(0.f, 0.f, 0.f, 0.f);
    float4 q4 = make_float4(0.f, 0.f, 0.f, 0.f);
#pragma unroll
    for (int k = 0; k < 8; k++) {
        int o = oe + k;
        float4 a4 = *(const float4*)&sWt[(o << 7) + p0];
        float4 g4 = *(const float4*)&sWt[((o + 128) << 7) + p0];
        float4 u4 = *(const float4*)&g_u[ubase + (o << 12) + l0 + p0];
        r[k].x = fmaf(a4.x, sigmoidf_(g4.x), u4.x);
        r[k].y = fmaf(a4.y, sigmoidf_(g4.y), u4.y);
        r[k].z = fmaf(a4.z, sigmoidf_(g4.z), u4.z);
        r[k].w = fmaf(a4.w, sigmoidf_(g4.w), u4.w);
        s4.x += r[k].x; s4.y += r[k].y; s4.z += r[k].z; s4.w += r[k].w;
        q4.x = fmaf(r[k].x, r[k].x, q4.x);
        q4.y = fmaf(r[k].y, r[k].y, q4.y);
        q4.z = fmaf(r[k].z, r[k].z, q4.z);
        q4.w = fmaf(r[k].w, r[k].w, q4.w);
    }
    *(float4*)&sPS[(w << 7) + p0] = s4;
    *(float4*)&sPQ[(w << 7) + p0] = q4;
    __syncthreads();

    if (t < 128) {
        float S = 0.f, Q = 0.f;
#pragma unroll
        for (int ww = 0; ww < 16; ww++) {
            S += sPS[(ww << 7) + t];
            Q += sPQ[(ww << 7) + t];
        }
        float mu = S * (1.0f / H_);
        float var = Q * (1.0f / H_) - mu * mu;
        sMu[t] = mu;
        sRs[t] = rsqrtf(var + 1e-5f);
    }
    __syncthreads();

    float4 mu4 = *(const float4*)&sMu[p0];
    float4 rs4 = *(const float4*)&sRs[p0];
#pragma unroll
    for (int k = 0; k < 8; k++) {
        int o = oe + k;
        float lw = sLnw[o], lb = sLnb[o];
        float4 v;
        v.x = (r[k].x - mu4.x) * rs4.x * lw + lb;
        v.y = (r[k].y - mu4.y) * rs4.y * lw + lb;
        v.z = (r[k].z - mu4.z) * rs4.z * lw + lb;
        v.w = (r[k].w - mu4.w) * rs4.w * lw + lb;
        *(float4*)&g_u[ubase + (o << 12) + l0 + p0] = v;
    }
}

// ---------------- kernel 4: mean-pool over L --------------------------------
__global__ void pool_kernel() {
    __shared__ float red[256];
    int t = threadIdx.x;
    const float* p = g_u + (size_t)blockIdx.x * L_;
    float s = 0.f;
    for (int i = t; i < L_; i += 256) s += p[i];
    red[t] = s;
    __syncthreads();
    for (int k = 128; k > 0; k >>= 1) {
        if (t < k) red[t] += red[t + k];
        __syncthreads();
    }
    if (t == 0) g_pool[blockIdx.x] = red[0] * (1.0f / L_);
}

// ---------------- kernel 5: decoder -----------------------------------------
__global__ void decode_kernel(const float* __restrict__ dec_w,
                              const float* __restrict__ dec_b,
                              float* __restrict__ pred) {
    int t = threadIdx.x;
    if (t >= B_ * DOUT) return;
    int b = t >> 3, o = t & 7;
    float acc = dec_b[o];
    for (int h = 0; h < H_; h++)
        acc = fmaf(dec_w[o * H_ + h], g_pool[b * H_ + h], acc);
    pred[t] = 1.0f / (1.0f + expf(-acc));
}

// ---------------- kernel 6: transpose (b,h,l) -> emb (b,l,h) -----------------
__global__ void transpose_kernel(float* __restrict__ emb) {
    __shared__ float tile[32][33];
    int b = blockIdx.z;
    int h0 = blockIdx.y * 32;
    int l0 = blockIdx.x * 32;
    int tx = threadIdx.x, ty = threadIdx.y;
#pragma unroll
    for (int i = 0; i < 32; i += 8)
        tile[ty + i][tx] = g_u[((b * H_ + h0 + ty + i) << 12) + l0 + tx];
    __syncthreads();
#pragma unroll
    for (int i = 0; i < 32; i += 8)
        emb[((size_t)(b * L_ + l0 + ty + i)) * H_ + h0 + tx] = tile[tx][ty + i];
}

// ---------------- launch ------------------------------------------------------
extern "C" void kernel_launch(void* const* d_in, const int* in_sizes, int n_in,
                              void* d_out, int out_size) {
    const float* x          = (const float*)d_in[0];
    // d_in[1] = times (unused)
    const float* enc_w      = (const float*)d_in[2];
    const float* enc_b      = (const float*)d_in[3];
    const float* log_dt     = (const float*)d_in[4];
    const float* log_A_real = (const float*)d_in[5];
    const float* A_imag     = (const float*)d_in[6];
    const float* C_re       = (const float*)d_in[7];
    const float* C_im       = (const float*)d_in[8];
    const float* Dskip      = (const float*)d_in[9];
    const float* conv_w     = (const float*)d_in[10];
    const float* conv_b     = (const float*)d_in[11];
    const float* ln_w       = (const float*)d_in[12];
    const float* ln_b       = (const float*)d_in[13];
    const float* dec_w      = (const float*)d_in[14];
    const float* dec_b      = (const float*)d_in[15];

    float* out = (float*)d_out;
    float* pred = out;           // (B, DOUT) = 256 floats
    float* emb  = out + B_ * DOUT;

    static const size_t glu_smem = GLU_SMEM_FLOATS * sizeof(float);
    cudaFuncSetAttribute(glu_ln_kernel,
                         cudaFuncAttributeMaxDynamicSharedMemorySize,
                         (int)glu_smem);

    precompute_kernel<<<(NL_ * H_ * N2_ + 255) / 256, 256>>>(
        log_dt, log_A_real, A_imag, C_re, C_im);

    encoder_kernel<<<dim3(L_ / 64, B_), 256>>>(x, enc_w, enc_b);

    for (int l = 0; l < NL_; l++) {
        scan_kernel<<<512, 128>>>(l, Dskip + l * H_);
        glu_ln_kernel<<<B_ * (L_ / 128), 512, glu_smem>>>(
            conv_w + (size_t)l * 2 * H_ * H_,
            conv_b + (size_t)l * 2 * H_,
            ln_w + (size_t)l * H_,
            ln_b + (size_t)l * H_);
    }

    pool_kernel<<<B_ * H_, 256>>>();
    decode_kernel<<<1, 256>>>(dec_w, dec_b, pred);
    transpose_kernel<<<dim3(L_ / 32, H_ / 32, B_), dim3(32, 8)>>>(emb);
}